// round 3
// baseline (speedup 1.0000x reference)
#include <cuda_runtime.h>

// Problem dims (fixed by the dataset)
#define BROWS 8192
#define DDIM  784
#define HDIM  500
#define CDIM  512
#define SDIM  16
#define CSDIM (CDIM * SDIM)      // 8192
#define NROWS2 (BROWS * SDIM)    // 131072

// -------- scratch (no allocations allowed; __device__ globals are the sanctioned path) ----
__device__ float g_h1[BROWS * HDIM];     // 16.4 MB
__device__ float g_h2[BROWS * HDIM];     // 16.4 MB
__device__ float g_cnorm[CDIM];          // |codebook_j|^2, computed in double
__device__ float g_rownorm[NROWS2];      // |obs_row|^2,   computed in double
__device__ int   g_codes[NROWS2];

// ============================================================================
// Codebook row norms in DOUBLE: cn[j] = fl32( sum_k (double)cb[j][k]^2 )
// One warp per row.
// ============================================================================
__global__ void cnorm_kernel(const float* __restrict__ cb, float* __restrict__ cn) {
    int warp = (blockIdx.x * blockDim.x + threadIdx.x) >> 5;
    int lane = threadIdx.x & 31;
    if (warp >= CDIM) return;
    const float* row = cb + (size_t)warp * CDIM;
    double s = 0.0;
    for (int k = lane; k < CDIM; k += 32) {
        double v = (double)row[k];
        s += v * v;
    }
    #pragma unroll
    for (int o = 16; o > 0; o >>= 1) s += __shfl_down_sync(0xffffffffu, s, o);
    if (lane == 0) cn[warp] = (float)s;
}

// ============================================================================
// Obs row norms in DOUBLE: A[r] = fl32( sum_k (double)obs[r][k]^2 ), one warp/row
// ============================================================================
__global__ void rownorm_kernel(const float* __restrict__ obs, float* __restrict__ rn) {
    int warp = (blockIdx.x * blockDim.x + threadIdx.x) >> 5;
    int lane = threadIdx.x & 31;
    if (warp >= NROWS2) return;
    const float* row = obs + (size_t)warp * CDIM;
    double s = 0.0;
    for (int k = lane; k < CDIM; k += 32) {
        double v = (double)row[k];
        s += v * v;
    }
    #pragma unroll
    for (int o = 16; o > 0; o >>= 1) s += __shfl_down_sync(0xffffffffu, s, o);
    if (lane == 0) rn[warp] = (float)s;
}

// ============================================================================
// Generic fp32 tiled GEMM: C[M,N] = act(A[M,K] @ B[K,N] + bias[N])
// BM=BN=128, BK=16, 256 threads, 8x8 microtile. M must be a multiple of 128.
// NUMERICS CONTRACT: each output element is accumulated by ONE fp32 accumulator
// with FFMA over k in strictly ascending order (matches cublas SIMT sgemm).
// ============================================================================
template<int RELU>
__global__ __launch_bounds__(256, 2)
void gemm_kernel(const float* __restrict__ A, const float* __restrict__ Bm,
                 const float* __restrict__ bias, float* __restrict__ C,
                 int M, int N, int K)
{
    const int BM = 128, BN = 128, BK = 16;
    __shared__ float As[BK][BM + 4];   // padded: transposed store, conflict-reduced
    __shared__ float Bs[BK][BN];

    int tid = threadIdx.x;
    int tr = tid >> 4;        // 0..15 (row group)
    int tc = tid & 15;        // 0..15 (col group)
    int row0 = blockIdx.y * BM;
    int col0 = blockIdx.x * BN;

    float acc[8][8];
    #pragma unroll
    for (int i = 0; i < 8; i++)
        #pragma unroll
        for (int j = 0; j < 8; j++) acc[i][j] = 0.f;

    for (int k0 = 0; k0 < K; k0 += BK) {
        // Load A tile [BM x BK], transposed into As[k][m].
        #pragma unroll
        for (int e = 0; e < 8; e++) {
            int l = tid + e * 256;
            int m = l >> 4;
            int k = l & 15;
            int gk = k0 + k;
            float v = 0.f;
            if (gk < K) v = A[(size_t)(row0 + m) * K + gk];
            As[k][m] = v;
        }
        // Load B tile [BK x BN], natural orientation (coalesced along n).
        #pragma unroll
        for (int e = 0; e < 8; e++) {
            int l = tid + e * 256;
            int k = l >> 7;
            int n = l & 127;
            int gk = k0 + k, gn = col0 + n;
            float v = 0.f;
            if (gk < K && gn < N) v = Bm[(size_t)gk * N + gn];
            Bs[k][n] = v;
        }
        __syncthreads();

        #pragma unroll
        for (int kk = 0; kk < BK; kk++) {
            float4 a0 = *(const float4*)(&As[kk][tr * 8]);
            float4 a1 = *(const float4*)(&As[kk][tr * 8 + 4]);
            float4 b0 = *(const float4*)(&Bs[kk][tc * 8]);
            float4 b1 = *(const float4*)(&Bs[kk][tc * 8 + 4]);
            float a[8] = {a0.x, a0.y, a0.z, a0.w, a1.x, a1.y, a1.z, a1.w};
            float b[8] = {b0.x, b0.y, b0.z, b0.w, b1.x, b1.y, b1.z, b1.w};
            #pragma unroll
            for (int i = 0; i < 8; i++)
                #pragma unroll
                for (int j = 0; j < 8; j++)
                    acc[i][j] = fmaf(a[i], b[j], acc[i][j]);
        }
        __syncthreads();
    }

    // Epilogue: bias + optional relu (plain FADD then FMAX, like XLA's fusion)
    #pragma unroll
    for (int i = 0; i < 8; i++) {
        int r = row0 + tr * 8 + i;
        #pragma unroll
        for (int j = 0; j < 8; j++) {
            int c = col0 + tc * 8 + j;
            if (c < N) {
                float v = __fadd_rn(acc[i][j], bias[c]);
                if (RELU) v = fmaxf(v, 0.f);
                C[(size_t)r * N + c] = v;
            }
        }
    }
}

// ============================================================================
// VQ: fused distance GEMM + argmin, replicating the reference fp32 op order:
//   d2_j = fl( fl( A_row - fl(2*B_j) ) + C_j )
// with A = |obs|^2 (double->fp32), C = |c_j|^2 (double->fp32),
// B = obs.c_j accumulated ascending-k fp32 FFMA (cublas-like).
// Each block: 128 rows x all 512 codes (4 code-tiles of 128), K=512.
// ============================================================================
__global__ __launch_bounds__(256, 2)
void vq_argmin_kernel(const float* __restrict__ obs, const float* __restrict__ cb,
                      const float* __restrict__ cnorm, const float* __restrict__ rownorm,
                      int* __restrict__ codes)
{
    const int BK = 16;
    __shared__ union {
        struct { float As[BK][132]; float Bs[BK][132]; } t;   // GEMM tiles
        struct { float rv[16][128]; int ri[16][128]; } r;     // argmin reduction
    } sm;

    int tid = threadIdx.x;
    int tr = tid >> 4;
    int tc = tid & 15;
    int row0 = blockIdx.x * 128;

    float best[8];
    int   bidx[8];
    float An[8];
    #pragma unroll
    for (int i = 0; i < 8; i++) {
        best[i] = 3.4e38f; bidx[i] = 0;
        An[i] = rownorm[row0 + tr * 8 + i];
    }

    for (int ct = 0; ct < 4; ct++) {           // code tiles of 128
        float acc[8][8];
        #pragma unroll
        for (int i = 0; i < 8; i++)
            #pragma unroll
            for (int j = 0; j < 8; j++) acc[i][j] = 0.f;

        for (int k0 = 0; k0 < CDIM; k0 += BK) {
            #pragma unroll
            for (int e = 0; e < 8; e++) {
                int l = tid + e * 256;
                int m = l >> 4;
                int k = l & 15;
                sm.t.As[k][m] = obs[(size_t)(row0 + m) * CDIM + k0 + k];
                sm.t.Bs[k][m] = cb[(size_t)(ct * 128 + m) * CDIM + k0 + k];
            }
            __syncthreads();
            #pragma unroll
            for (int kk = 0; kk < BK; kk++) {
                float4 a0 = *(const float4*)(&sm.t.As[kk][tr * 8]);
                float4 a1 = *(const float4*)(&sm.t.As[kk][tr * 8 + 4]);
                float4 b0 = *(const float4*)(&sm.t.Bs[kk][tc * 8]);
                float4 b1 = *(const float4*)(&sm.t.Bs[kk][tc * 8 + 4]);
                float a[8] = {a0.x, a0.y, a0.z, a0.w, a1.x, a1.y, a1.z, a1.w};
                float b[8] = {b0.x, b0.y, b0.z, b0.w, b1.x, b1.y, b1.z, b1.w};
                #pragma unroll
                for (int i = 0; i < 8; i++)
                    #pragma unroll
                    for (int j = 0; j < 8; j++)
                        acc[i][j] = fmaf(a[i], b[j], acc[i][j]);
            }
            __syncthreads();
        }

        // d2 = (A - 2*B) + C with explicit fp32 roundings, no fma contraction.
        #pragma unroll
        for (int j = 0; j < 8; j++) {
            int code = ct * 128 + tc * 8 + j;
            float cn = cnorm[code];
            #pragma unroll
            for (int i = 0; i < 8; i++) {
                float twob = __fmul_rn(2.0f, acc[i][j]);   // exact (x2)
                float t2   = __fadd_rn(An[i], -twob);      // fl(A - 2B)
                float d    = __fadd_rn(t2, cn);            // fl(.. + C)
                if (d < best[i]) { best[i] = d; bidx[i] = code; }  // first-index ties
            }
        }
    }

    __syncthreads();   // done with sm.t before overlaying sm.r
    #pragma unroll
    for (int i = 0; i < 8; i++) {
        sm.r.rv[tc][tr * 8 + i] = best[i];
        sm.r.ri[tc][tr * 8 + i] = bidx[i];
    }
    __syncthreads();
    if (tid < 128) {
        float bv = sm.r.rv[0][tid];
        int   bi = sm.r.ri[0][tid];
        #pragma unroll
        for (int t = 1; t < 16; t++) {
            float v = sm.r.rv[t][tid];
            int  ix = sm.r.ri[t][tid];
            if (v < bv || (v == bv && ix < bi)) { bv = v; bi = ix; }
        }
        codes[row0 + tid] = bi;
    }
}

// ============================================================================
// latent[row] = codebook[codes[row]]  (512 floats per row, float4 copies)
// ============================================================================
__global__ void gather_latent_kernel(const int* __restrict__ codes,
                                     const float* __restrict__ cb,
                                     float* __restrict__ latent)
{
    int row = blockIdx.x;
    int c = codes[row];
    const float4* src = (const float4*)(cb + (size_t)c * CDIM);
    float4* dst = (float4*)(latent + (size_t)row * CDIM);
    dst[threadIdx.x] = src[threadIdx.x];   // 128 threads x 16B = 512 floats
}

// ============================================================================
// launch
// ============================================================================
extern "C" void kernel_launch(void* const* d_in, const int* in_sizes, int n_in,
                              void* d_out, int out_size)
{
    const float* x    = (const float*)d_in[0];
    const float* ew1  = (const float*)d_in[1];
    const float* eb1  = (const float*)d_in[2];
    const float* ew2  = (const float*)d_in[3];
    const float* eb2  = (const float*)d_in[4];
    const float* ew3  = (const float*)d_in[5];
    const float* eb3  = (const float*)d_in[6];
    const float* cb   = (const float*)d_in[7];
    const float* dw1  = (const float*)d_in[8];
    const float* db1  = (const float*)d_in[9];
    const float* dw2  = (const float*)d_in[10];
    const float* db2  = (const float*)d_in[11];

    float* out        = (float*)d_out;
    float* out_recon  = out;                                     // [8192, 784]
    float* out_obs    = out + (size_t)BROWS * DDIM;              // [131072, 512]
    float* out_latent = out_obs + (size_t)BROWS * CSDIM;         // [131072, 512]

    float *h1, *h2, *cn, *rn; int* codes;
    cudaGetSymbolAddress((void**)&h1, g_h1);
    cudaGetSymbolAddress((void**)&h2, g_h2);
    cudaGetSymbolAddress((void**)&cn, g_cnorm);
    cudaGetSymbolAddress((void**)&rn, g_rownorm);
    cudaGetSymbolAddress((void**)&codes, g_codes);

    // codebook row norms (double-accurate)
    cnorm_kernel<<<CDIM / 8, 256>>>(cb, cn);

    // encoder
    gemm_kernel<1><<<dim3(4, 64), 256>>>(x,  ew1, eb1, h1, BROWS, HDIM, DDIM);   // 8192x500
    gemm_kernel<1><<<dim3(4, 64), 256>>>(h1, ew2, eb2, h2, BROWS, HDIM, HDIM);   // 8192x500
    gemm_kernel<0><<<dim3(64, 64), 256>>>(h2, ew3, eb3, out_obs, BROWS, CSDIM, HDIM); // obs

    // obs row norms (double-accurate), then vector quantization
    rownorm_kernel<<<NROWS2 / 8, 256>>>(out_obs, rn);
    vq_argmin_kernel<<<NROWS2 / 128, 256>>>(out_obs, cb, cn, rn, codes);
    gather_latent_kernel<<<NROWS2, 128>>>(codes, cb, out_latent);

    // decoder (z = latent viewed as [8192, 8192], contiguous by construction)
    gemm_kernel<1><<<dim3(4, 64), 256>>>(out_latent, dw1, db1, h1, BROWS, HDIM, CSDIM);
    gemm_kernel<0><<<dim3(7, 64), 256>>>(h1, dw2, db2, out_recon, BROWS, DDIM, HDIM);
}

// round 4
// speedup vs baseline: 1.2223x; 1.2223x over previous
#include <cuda_runtime.h>
#include <cstdint>

// Problem dims (fixed by the dataset)
#define BROWS 8192
#define DDIM  784
#define HDIM  500
#define CDIM  512
#define SDIM  16
#define CSDIM (CDIM * SDIM)      // 8192
#define NROWS2 (BROWS * SDIM)    // 131072

// -------- scratch (no allocations allowed) ----
__device__ float g_h1[BROWS * HDIM];
__device__ float g_h2[BROWS * HDIM];
__device__ float g_cnorm[CDIM];
__device__ float g_rownorm[NROWS2];
__device__ int   g_codes[NROWS2];

// ---------------- packed f32x2 helpers (sm_100+: fma.rn.f32x2) ----------------
__device__ __forceinline__ uint64_t pack_dup(float x) {
    uint64_t r;
    asm("mov.b64 %0, {%1, %1};" : "=l"(r) : "f"(x));
    return r;
}
__device__ __forceinline__ void ffma2(uint64_t& d, uint64_t a, uint64_t b) {
    // per-lane IEEE fma: d.lo=fma(a.lo,b.lo,d.lo), d.hi=fma(a.hi,b.hi,d.hi)
    asm("fma.rn.f32x2 %0, %1, %2, %0;" : "+l"(d) : "l"(a), "l"(b));
}
__device__ __forceinline__ float2 unpack2(uint64_t v) {
    float lo, hi;
    asm("mov.b64 {%0, %1}, %2;" : "=f"(lo), "=f"(hi) : "l"(v));
    return make_float2(lo, hi);
}

// ============================================================================
// Codebook row norms in DOUBLE (one warp per row)
// ============================================================================
__global__ void cnorm_kernel(const float* __restrict__ cb, float* __restrict__ cn) {
    int warp = (blockIdx.x * blockDim.x + threadIdx.x) >> 5;
    int lane = threadIdx.x & 31;
    if (warp >= CDIM) return;
    const float* row = cb + (size_t)warp * CDIM;
    double s = 0.0;
    for (int k = lane; k < CDIM; k += 32) {
        double v = (double)row[k];
        s += v * v;
    }
    #pragma unroll
    for (int o = 16; o > 0; o >>= 1) s += __shfl_down_sync(0xffffffffu, s, o);
    if (lane == 0) cn[warp] = (float)s;
}

// ============================================================================
// Obs row norms in DOUBLE (one warp per row)
// ============================================================================
__global__ void rownorm_kernel(const float* __restrict__ obs, float* __restrict__ rn) {
    int warp = (blockIdx.x * blockDim.x + threadIdx.x) >> 5;
    int lane = threadIdx.x & 31;
    if (warp >= NROWS2) return;
    const float* row = obs + (size_t)warp * CDIM;
    double s = 0.0;
    for (int k = lane; k < CDIM; k += 32) {
        double v = (double)row[k];
        s += v * v;
    }
    #pragma unroll
    for (int o = 16; o > 0; o >>= 1) s += __shfl_down_sync(0xffffffffu, s, o);
    if (lane == 0) rn[warp] = (float)s;
}

// ============================================================================
// BIG fp32 GEMM: C[M,N] = act(A @ B + bias). BM=256, BN=128, BK=16,
// 256 threads, 16x8 per thread, FFMA2 (row-paired). M % 256 == 0 required.
// NUMERICS: one fp32 accumulator per output, FFMA over ascending k.
// ============================================================================
template<int RELU>
__global__ __launch_bounds__(256, 1)
void gemm_big(const float* __restrict__ A, const float* __restrict__ Bm,
              const float* __restrict__ bias, float* __restrict__ C,
              int N, int K)
{
    const int BM = 256, BN = 128, BK = 16;
    __shared__ float As[BK][BM];        // transposed: As[k][m]
    __shared__ float Bs[BK][BN + 4];    // natural:    Bs[k][n]

    int tid = threadIdx.x;
    int tr = tid >> 4;        // 0..15 -> rows tr*16..+15
    int tc = tid & 15;        // 0..15 -> cols tc*8..+7
    int row0 = blockIdx.y * BM;
    int col0 = blockIdx.x * BN;

    const float* Arow = A + (size_t)(row0 + tid) * K;   // thread owns one A row
    int bk = tid >> 4;                // B: k index within tile
    int bn = (tid & 15) * 8;          // B: n offset within tile

    float4 pa[4], pb[2];
    // prefetch tile k0 = 0
    #pragma unroll
    for (int d = 0; d < 4; d++) {
        int gk = d * 4;
        pa[d] = (gk < K) ? *(const float4*)(Arow + gk) : make_float4(0.f,0.f,0.f,0.f);
    }
    #pragma unroll
    for (int d = 0; d < 2; d++) {
        int gn = col0 + bn + d * 4;
        pb[d] = (bk < K && gn < N) ? *(const float4*)(Bm + (size_t)bk * N + gn)
                                   : make_float4(0.f,0.f,0.f,0.f);
    }

    uint64_t acc2[8][8];
    #pragma unroll
    for (int p = 0; p < 8; p++)
        #pragma unroll
        for (int j = 0; j < 8; j++) acc2[p][j] = 0ull;

    for (int k0 = 0; k0 < K; k0 += BK) {
        // commit prefetched tile to smem
        #pragma unroll
        for (int d = 0; d < 4; d++) {
            As[d*4+0][tid] = pa[d].x;
            As[d*4+1][tid] = pa[d].y;
            As[d*4+2][tid] = pa[d].z;
            As[d*4+3][tid] = pa[d].w;
        }
        *(float4*)(&Bs[bk][bn])     = pb[0];
        *(float4*)(&Bs[bk][bn + 4]) = pb[1];
        __syncthreads();

        // prefetch next tile
        int kn = k0 + BK;
        if (kn < K) {
            #pragma unroll
            for (int d = 0; d < 4; d++) {
                int gk = kn + d * 4;
                pa[d] = (gk < K) ? *(const float4*)(Arow + gk) : make_float4(0.f,0.f,0.f,0.f);
            }
            #pragma unroll
            for (int d = 0; d < 2; d++) {
                int gk = kn + bk;
                int gn = col0 + bn + d * 4;
                pb[d] = (gk < K && gn < N) ? *(const float4*)(Bm + (size_t)gk * N + gn)
                                           : make_float4(0.f,0.f,0.f,0.f);
            }
        }

        #pragma unroll
        for (int kk = 0; kk < BK; kk++) {
            uint64_t ap[8];
            #pragma unroll
            for (int p = 0; p < 4; p++) {
                ulonglong2 v = *(const ulonglong2*)(&As[kk][tr * 16 + p * 4]);
                ap[p*2]   = v.x;
                ap[p*2+1] = v.y;
            }
            float4 b0 = *(const float4*)(&Bs[kk][tc * 8]);
            float4 b1 = *(const float4*)(&Bs[kk][tc * 8 + 4]);
            uint64_t bd[8];
            bd[0] = pack_dup(b0.x); bd[1] = pack_dup(b0.y);
            bd[2] = pack_dup(b0.z); bd[3] = pack_dup(b0.w);
            bd[4] = pack_dup(b1.x); bd[5] = pack_dup(b1.y);
            bd[6] = pack_dup(b1.z); bd[7] = pack_dup(b1.w);
            #pragma unroll
            for (int p = 0; p < 8; p++)
                #pragma unroll
                for (int j = 0; j < 8; j++)
                    ffma2(acc2[p][j], ap[p], bd[j]);
        }
        __syncthreads();
    }

    // epilogue: bias + optional relu, float4 stores
    float bb[8];
    #pragma unroll
    for (int j = 0; j < 8; j++) {
        int c = col0 + tc * 8 + j;
        bb[j] = (c < N) ? bias[c] : 0.f;
    }
    #pragma unroll
    for (int p = 0; p < 8; p++) {
        #pragma unroll
        for (int half = 0; half < 2; half++) {
            int r = row0 + tr * 16 + p * 2 + half;
            float v[8];
            #pragma unroll
            for (int j = 0; j < 8; j++) {
                float2 u = unpack2(acc2[p][j]);
                float t = __fadd_rn(half ? u.y : u.x, bb[j]);
                if (RELU) t = fmaxf(t, 0.f);
                v[j] = t;
            }
            int c0 = col0 + tc * 8;
            if (c0 < N)
                *(float4*)(C + (size_t)r * N + c0)     = make_float4(v[0], v[1], v[2], v[3]);
            if (c0 + 4 < N)
                *(float4*)(C + (size_t)r * N + c0 + 4) = make_float4(v[4], v[5], v[6], v[7]);
        }
    }
}

// ============================================================================
// SMALL fp32 GEMM: 128x128 block, 8x8 per thread, FFMA2. (enc1/enc2/dec2)
// ============================================================================
template<int RELU>
__global__ __launch_bounds__(256, 2)
void gemm_small(const float* __restrict__ A, const float* __restrict__ Bm,
                const float* __restrict__ bias, float* __restrict__ C,
                int N, int K)
{
    const int BM = 128, BN = 128, BK = 16;
    __shared__ float As[BK][BM + 4];
    __shared__ float Bs[BK][BN];

    int tid = threadIdx.x;
    int tr = tid >> 4;
    int tc = tid & 15;
    int row0 = blockIdx.y * BM;
    int col0 = blockIdx.x * BN;

    uint64_t acc2[4][8];
    #pragma unroll
    for (int p = 0; p < 4; p++)
        #pragma unroll
        for (int j = 0; j < 8; j++) acc2[p][j] = 0ull;

    for (int k0 = 0; k0 < K; k0 += BK) {
        #pragma unroll
        for (int e = 0; e < 8; e++) {
            int l = tid + e * 256;
            int m = l >> 4;
            int k = l & 15;
            int gk = k0 + k;
            float v = 0.f;
            if (gk < K) v = A[(size_t)(row0 + m) * K + gk];
            As[k][m] = v;
        }
        #pragma unroll
        for (int e = 0; e < 8; e++) {
            int l = tid + e * 256;
            int k = l >> 7;
            int n = l & 127;
            int gk = k0 + k, gn = col0 + n;
            float v = 0.f;
            if (gk < K && gn < N) v = Bm[(size_t)gk * N + gn];
            Bs[k][n] = v;
        }
        __syncthreads();

        #pragma unroll
        for (int kk = 0; kk < BK; kk++) {
            ulonglong2 va0 = *(const ulonglong2*)(&As[kk][tr * 8]);
            ulonglong2 va1 = *(const ulonglong2*)(&As[kk][tr * 8 + 4]);
            uint64_t ap[4] = {va0.x, va0.y, va1.x, va1.y};
            float4 b0 = *(const float4*)(&Bs[kk][tc * 8]);
            float4 b1 = *(const float4*)(&Bs[kk][tc * 8 + 4]);
            uint64_t bd[8];
            bd[0] = pack_dup(b0.x); bd[1] = pack_dup(b0.y);
            bd[2] = pack_dup(b0.z); bd[3] = pack_dup(b0.w);
            bd[4] = pack_dup(b1.x); bd[5] = pack_dup(b1.y);
            bd[6] = pack_dup(b1.z); bd[7] = pack_dup(b1.w);
            #pragma unroll
            for (int p = 0; p < 4; p++)
                #pragma unroll
                for (int j = 0; j < 8; j++)
                    ffma2(acc2[p][j], ap[p], bd[j]);
        }
        __syncthreads();
    }

    #pragma unroll
    for (int p = 0; p < 4; p++) {
        #pragma unroll
        for (int half = 0; half < 2; half++) {
            int r = row0 + tr * 8 + p * 2 + half;
            #pragma unroll
            for (int j = 0; j < 8; j++) {
                int c = col0 + tc * 8 + j;
                if (c < N) {
                    float2 u = unpack2(acc2[p][j]);
                    float v = __fadd_rn(half ? u.y : u.x, bias[c]);
                    if (RELU) v = fmaxf(v, 0.f);
                    C[(size_t)r * N + c] = v;
                }
            }
        }
    }
}

// ============================================================================
// VQ: fused distance GEMM + argmin, 256 rows/block x all 512 codes (4 tiles).
//   d2 = fl( fl(A - fl(2*B)) + C ),  A,C double-accurate, B ascending-k fp32.
// ============================================================================
__global__ __launch_bounds__(256, 1)
void vq_argmin_big(const float* __restrict__ obs, const float* __restrict__ cb,
                   const float* __restrict__ cnorm, const float* __restrict__ rownorm,
                   int* __restrict__ codes)
{
    const int BM = 256, BN = 128, BK = 16;
    __shared__ union {
        struct { float As[BK][BM]; float Bs[BK][BN]; } t;
        struct { float rv[16][BM]; int ri[16][BM]; } r;
    } sm;

    int tid = threadIdx.x;
    int tr = tid >> 4;
    int tc = tid & 15;
    int row0 = blockIdx.x * BM;

    const float* Arow = obs + (size_t)(row0 + tid) * CDIM;
    int bcode = tid & 127;            // B: code row handled by this thread
    int bkh   = (tid >> 7) * 8;       // B: k-half offset (0 or 8)

    float best[16];
    int   bidx[16];
    #pragma unroll
    for (int i = 0; i < 16; i++) { best[i] = 3.4e38f; bidx[i] = 0; }

    for (int ct = 0; ct < 4; ct++) {
        const float* Brow = cb + (size_t)(ct * 128 + bcode) * CDIM + bkh;

        // prefetch k0 = 0
        float4 pa[4], pb[2];
        #pragma unroll
        for (int d = 0; d < 4; d++) pa[d] = *(const float4*)(Arow + d * 4);
        #pragma unroll
        for (int d = 0; d < 2; d++) pb[d] = *(const float4*)(Brow + d * 4);

        uint64_t acc2[8][8];
        #pragma unroll
        for (int p = 0; p < 8; p++)
            #pragma unroll
            for (int j = 0; j < 8; j++) acc2[p][j] = 0ull;

        for (int k0 = 0; k0 < CDIM; k0 += BK) {
            #pragma unroll
            for (int d = 0; d < 4; d++) {
                sm.t.As[d*4+0][tid] = pa[d].x;
                sm.t.As[d*4+1][tid] = pa[d].y;
                sm.t.As[d*4+2][tid] = pa[d].z;
                sm.t.As[d*4+3][tid] = pa[d].w;
            }
            #pragma unroll
            for (int d = 0; d < 2; d++) {
                sm.t.Bs[bkh + d*4 + 0][bcode] = pb[d].x;
                sm.t.Bs[bkh + d*4 + 1][bcode] = pb[d].y;
                sm.t.Bs[bkh + d*4 + 2][bcode] = pb[d].z;
                sm.t.Bs[bkh + d*4 + 3][bcode] = pb[d].w;
            }
            __syncthreads();

            int kn = k0 + BK;
            if (kn < CDIM) {
                #pragma unroll
                for (int d = 0; d < 4; d++) pa[d] = *(const float4*)(Arow + kn + d * 4);
                #pragma unroll
                for (int d = 0; d < 2; d++) pb[d] = *(const float4*)(Brow + kn + d * 4);
            }

            #pragma unroll
            for (int kk = 0; kk < BK; kk++) {
                uint64_t ap[8];
                #pragma unroll
                for (int p = 0; p < 4; p++) {
                    ulonglong2 v = *(const ulonglong2*)(&sm.t.As[kk][tr * 16 + p * 4]);
                    ap[p*2]   = v.x;
                    ap[p*2+1] = v.y;
                }
                float4 b0 = *(const float4*)(&sm.t.Bs[kk][tc * 8]);
                float4 b1 = *(const float4*)(&sm.t.Bs[kk][tc * 8 + 4]);
                uint64_t bd[8];
                bd[0] = pack_dup(b0.x); bd[1] = pack_dup(b0.y);
                bd[2] = pack_dup(b0.z); bd[3] = pack_dup(b0.w);
                bd[4] = pack_dup(b1.x); bd[5] = pack_dup(b1.y);
                bd[6] = pack_dup(b1.z); bd[7] = pack_dup(b1.w);
                #pragma unroll
                for (int p = 0; p < 8; p++)
                    #pragma unroll
                    for (int j = 0; j < 8; j++)
                        ffma2(acc2[p][j], ap[p], bd[j]);
            }
            __syncthreads();
        }

        // d2 epilogue for this code tile (exact reference op order)
        #pragma unroll
        for (int j = 0; j < 8; j++) {
            int code = ct * 128 + tc * 8 + j;
            float cn = cnorm[code];
            #pragma unroll
            for (int p = 0; p < 8; p++) {
                float2 u = unpack2(acc2[p][j]);
                #pragma unroll
                for (int half = 0; half < 2; half++) {
                    int i = p * 2 + half;
                    float An = rownorm[row0 + tr * 16 + i];   // L1-resident re-read
                    float twob = __fmul_rn(2.0f, half ? u.y : u.x);
                    float t2   = __fadd_rn(An, -twob);
                    float d    = __fadd_rn(t2, cn);
                    if (d < best[i]) { best[i] = d; bidx[i] = code; }
                }
            }
        }
    }

    __syncthreads();   // tiles dead; overlay reduction arrays
    #pragma unroll
    for (int i = 0; i < 16; i++) {
        sm.r.rv[tc][tr * 16 + i] = best[i];
        sm.r.ri[tc][tr * 16 + i] = bidx[i];
    }
    __syncthreads();
    {
        float bv = sm.r.rv[0][tid];
        int   bi = sm.r.ri[0][tid];
        #pragma unroll
        for (int t = 1; t < 16; t++) {
            float v = sm.r.rv[t][tid];
            int  ix = sm.r.ri[t][tid];
            if (v < bv || (v == bv && ix < bi)) { bv = v; bi = ix; }
        }
        codes[row0 + tid] = bi;
    }
}

// ============================================================================
// latent[row] = codebook[codes[row]]
// ============================================================================
__global__ void gather_latent_kernel(const int* __restrict__ codes,
                                     const float* __restrict__ cb,
                                     float* __restrict__ latent)
{
    int row = blockIdx.x;
    int c = codes[row];
    const float4* src = (const float4*)(cb + (size_t)c * CDIM);
    float4* dst = (float4*)(latent + (size_t)row * CDIM);
    dst[threadIdx.x] = src[threadIdx.x];
}

// ============================================================================
// launch
// ============================================================================
extern "C" void kernel_launch(void* const* d_in, const int* in_sizes, int n_in,
                              void* d_out, int out_size)
{
    const float* x    = (const float*)d_in[0];
    const float* ew1  = (const float*)d_in[1];
    const float* eb1  = (const float*)d_in[2];
    const float* ew2  = (const float*)d_in[3];
    const float* eb2  = (const float*)d_in[4];
    const float* ew3  = (const float*)d_in[5];
    const float* eb3  = (const float*)d_in[6];
    const float* cb   = (const float*)d_in[7];
    const float* dw1  = (const float*)d_in[8];
    const float* db1  = (const float*)d_in[9];
    const float* dw2  = (const float*)d_in[10];
    const float* db2  = (const float*)d_in[11];

    float* out        = (float*)d_out;
    float* out_recon  = out;                                     // [8192, 784]
    float* out_obs    = out + (size_t)BROWS * DDIM;              // [131072, 512]
    float* out_latent = out_obs + (size_t)BROWS * CSDIM;         // [131072, 512]

    float *h1, *h2, *cn, *rn; int* codes;
    cudaGetSymbolAddress((void**)&h1, g_h1);
    cudaGetSymbolAddress((void**)&h2, g_h2);
    cudaGetSymbolAddress((void**)&cn, g_cnorm);
    cudaGetSymbolAddress((void**)&rn, g_rownorm);
    cudaGetSymbolAddress((void**)&codes, g_codes);

    // codebook row norms (double-accurate)
    cnorm_kernel<<<CDIM / 8, 256>>>(cb, cn);

    // encoder
    gemm_small<1><<<dim3(4, 64), 256>>>(x,  ew1, eb1, h1, HDIM, DDIM);
    gemm_small<1><<<dim3(4, 64), 256>>>(h1, ew2, eb2, h2, HDIM, HDIM);
    gemm_big<0><<<dim3(64, 32), 256>>>(h2, ew3, eb3, out_obs, CSDIM, HDIM);

    // obs row norms (double-accurate), then vector quantization
    rownorm_kernel<<<NROWS2 / 8, 256>>>(out_obs, rn);
    vq_argmin_big<<<NROWS2 / 256, 256>>>(out_obs, cb, cn, rn, codes);
    gather_latent_kernel<<<NROWS2, 128>>>(codes, cb, out_latent);

    // decoder
    gemm_big<1><<<dim3(4, 32), 256>>>(out_latent, dw1, db1, h1, HDIM, CSDIM);
    gemm_small<0><<<dim3(7, 64), 256>>>(h1, dw2, db2, out_recon, DDIM, HDIM);
}